// round 4
// baseline (speedup 1.0000x reference)
#include <cuda_runtime.h>
#include <cstdint>

#define CPS    16
#define ENC    128
#define BATCH  4
#define HW     160
#define NGRID  10
#define NPATCH 100
#define NROWS  (BATCH * NPATCH)   // 400
#define CCH    256
#define BR     8                  // rows per MLP block
#define CONVBLK 200               // conv main blocks per branch (25600 thr / 128)
#define TPB     4                 // transpose helper blocks per branch

// Scratch (allocation-free)
__device__ float g_X[2][NROWS * CCH];          // conv output, patch-major
__device__ float g_E[2][NROWS * ENC];          // embeddings
__device__ float g_W1T[2][CCH * CCH];          // W1 transposed: [k][j]
__device__ float g_W2T[2][CCH * ENC];          // W2 transposed: [k][o]

// ---- packed f32x2 helpers (sm_103a FFMA2 path) -----------------------------
__device__ __forceinline__ void ffma2(unsigned long long& acc,
                                      unsigned long long x,
                                      unsigned long long w) {
    asm("fma.rn.f32x2 %0, %1, %2, %0;" : "+l"(acc) : "l"(x), "l"(w));
}
__device__ __forceinline__ unsigned long long pk2(float lo, float hi) {
    unsigned long long r;
    asm("mov.b64 %0, {%1, %2};" : "=l"(r) : "f"(lo), "f"(hi));
    return r;
}
__device__ __forceinline__ void upk2(unsigned long long v, float& lo, float& hi) {
    asm("mov.b64 {%0, %1}, %2;" : "=f"(lo), "=f"(hi) : "l"(v));
}

// ---------------------------------------------------------------------------
// Kernel A: 1x1 conv (channel reduction) + bias + relu, patch-reordered write.
// HBM-bound: reads 210 MB once. Thread = 4 consecutive x via float4, unroll 16
// -> 8 KB in flight per warp. Extra blocks (idx >= CONVBLK) transpose W into
// g_W1T/g_W2T, hidden under the HBM-bound main work.
// ---------------------------------------------------------------------------
__global__ void conv_kernel(const float* __restrict__ f1,
                            const float* __restrict__ f2,
                            const float* __restrict__ w_img,
                            const float* __restrict__ b_img,
                            const float* __restrict__ w_dep,
                            const float* __restrict__ b_dep,
                            const float* __restrict__ iw1,
                            const float* __restrict__ iw2,
                            const float* __restrict__ dw1,
                            const float* __restrict__ dw2)
{
    const int br  = blockIdx.y;
    const int tid = threadIdx.x;

    if (blockIdx.x >= CONVBLK) {
        // ---- weight transpose side-blocks (runs concurrently with conv) ----
        const int tb = blockIdx.x - CONVBLK;              // 0..TPB-1
        const float* __restrict__ W1 = br ? dw1 : iw1;    // [j][k] 256x256
        const float* __restrict__ W2 = br ? dw2 : iw2;    // [o][k] 128x256
        float* __restrict__ W1T = g_W1T[br];
        float* __restrict__ W2T = g_W2T[br];
        for (int idx = tb * 128 + tid; idx < CCH * CCH; idx += TPB * 128) {
            int k = idx >> 8, j = idx & 255;
            W1T[idx] = W1[j * CCH + k];                   // W1T[k][j]
        }
        for (int idx = tb * 128 + tid; idx < CCH * ENC; idx += TPB * 128) {
            int k = idx >> 7, o = idx & 127;
            W2T[idx] = W2[o * CCH + k];                   // W2T[k][o]
        }
        return;
    }

    const float* __restrict__ feat = br ? f2 : f1;
    const float* __restrict__ cw   = br ? w_dep : w_img;
    const float  bias              = br ? b_dep[0] : b_img[0];

    __shared__ float ws[CCH];
    ws[tid]       = cw[tid];
    ws[tid + 128] = cw[tid + 128];
    __syncthreads();

    const int g   = blockIdx.x * 128 + tid;   // 0..25599
    const int xq  = g % 40;
    const int row = g / 40;                   // 0..639
    const int x   = xq * 4;
    const int y   = row % HW;
    const int b   = row / HW;

    const float* __restrict__ base =
        feat + (size_t)b * CCH * (HW * HW) + (size_t)y * HW + x;

    float a0 = 0.f, a1 = 0.f, a2 = 0.f, a3 = 0.f;
    #pragma unroll 16
    for (int c = 0; c < CCH; c++) {
        float4 v = *reinterpret_cast<const float4*>(base + (size_t)c * (HW * HW));
        float  w = ws[c];
        a0 = fmaf(w, v.x, a0);
        a1 = fmaf(w, v.y, a1);
        a2 = fmaf(w, v.z, a2);
        a3 = fmaf(w, v.w, a3);
    }
    float4 o;
    o.x = fmaxf(a0 + bias, 0.f);
    o.y = fmaxf(a1 + bias, 0.f);
    o.z = fmaxf(a2 + bias, 0.f);
    o.w = fmaxf(a3 + bias, 0.f);

    const int pv = y >> 4, i  = y & 15;
    const int ph = x >> 4, j0 = x & 15;       // 4-aligned, same patch
    const int p  = (b * NGRID + pv) * NGRID + ph;
    *reinterpret_cast<float4*>(&g_X[br][(p << 8) + (i << 4) + j0]) = o;
}

// ---------------------------------------------------------------------------
// Kernel B: per-branch MLP  relu(X @ W1^T) @ W2^T  + LayerNorm(128).
// grid = (50, 2), block = 256, 8 rows per block.
// Transposed W -> coalesced 128B warp loads (1 line/LDG instead of 32).
// Row-pairs packed into f32x2 accumulators (FFMA2, 2x fp32 throughput).
// ---------------------------------------------------------------------------
__global__ void mlp_kernel(const float* __restrict__ g_img,
                           const float* __restrict__ be_img,
                           const float* __restrict__ g_dep,
                           const float* __restrict__ be_dep)
{
    const int br  = blockIdx.y;
    const float* __restrict__ W1T = g_W1T[br];
    const float* __restrict__ W2T = g_W2T[br];
    const float* __restrict__ lng = br ? g_dep  : g_img;
    const float* __restrict__ lnb = br ? be_dep : be_img;

    const int row0 = blockIdx.x * BR;
    const int tid  = threadIdx.x;

    __shared__ float xsT[CCH * BR];   // [k][r]
    __shared__ float hsT[CCH * BR];   // [k][r]
    __shared__ float os [BR * ENC];   // [r][o]

    // load X rows transposed (coalesced reads)
    #pragma unroll
    for (int i = 0; i < BR; i++)
        xsT[tid * BR + i] = g_X[br][(row0 + i) * CCH + tid];
    __syncthreads();

    // GEMM1: h[r][j] = relu( sum_k x[r][k] * W1[j][k] ),  j = tid
    {
        unsigned long long a01 = 0, a23 = 0, a45 = 0, a67 = 0;
        const float* __restrict__ wp = W1T + tid;     // W1T[k*256 + j]
        #pragma unroll 16
        for (int k = 0; k < CCH; k++) {
            float w = __ldg(wp + k * CCH);            // coalesced 128B/warp
            unsigned long long ww = pk2(w, w);
            const ulonglong2* xv =
                reinterpret_cast<const ulonglong2*>(&xsT[k * BR]);
            ulonglong2 x0 = xv[0];                    // rows 0-3 (broadcast)
            ulonglong2 x1 = xv[1];                    // rows 4-7
            ffma2(a01, x0.x, ww);
            ffma2(a23, x0.y, ww);
            ffma2(a45, x1.x, ww);
            ffma2(a67, x1.y, ww);
        }
        float h[8];
        upk2(a01, h[0], h[1]); upk2(a23, h[2], h[3]);
        upk2(a45, h[4], h[5]); upk2(a67, h[6], h[7]);
        float4 h0, h1;
        h0.x = fmaxf(h[0], 0.f); h0.y = fmaxf(h[1], 0.f);
        h0.z = fmaxf(h[2], 0.f); h0.w = fmaxf(h[3], 0.f);
        h1.x = fmaxf(h[4], 0.f); h1.y = fmaxf(h[5], 0.f);
        h1.z = fmaxf(h[6], 0.f); h1.w = fmaxf(h[7], 0.f);
        *reinterpret_cast<float4*>(&hsT[tid * BR])     = h0;
        *reinterpret_cast<float4*>(&hsT[tid * BR + 4]) = h1;
    }
    __syncthreads();

    // GEMM2: out[r][o] = sum_k h[r][k] * W2[o][k]
    {
        const int o  = tid & 127;
        const int rb = (tid >> 7) * 4;                // rows rb..rb+3
        unsigned long long b01 = 0, b23 = 0;
        const float* __restrict__ wp = W2T + o;       // W2T[k*128 + o]
        #pragma unroll 16
        for (int k = 0; k < CCH; k++) {
            float w = __ldg(wp + k * ENC);
            unsigned long long ww = pk2(w, w);
            ulonglong2 hv =
                *reinterpret_cast<const ulonglong2*>(&hsT[k * BR + rb]);
            ffma2(b01, hv.x, ww);
            ffma2(b23, hv.y, ww);
        }
        float o0, o1, o2, o3;
        upk2(b01, o0, o1); upk2(b23, o2, o3);
        os[(rb + 0) * ENC + o] = o0;
        os[(rb + 1) * ENC + o] = o1;
        os[(rb + 2) * ENC + o] = o2;
        os[(rb + 3) * ENC + o] = o3;
    }
    __syncthreads();

    // LayerNorm: warp w handles row w
    {
        const int w    = tid >> 5;
        const int lane = tid & 31;
        float4 v = *reinterpret_cast<const float4*>(&os[w * ENC + lane * 4]);
        float s = v.x + v.y + v.z + v.w;
        float q = v.x * v.x + v.y * v.y + v.z * v.z + v.w * v.w;
        #pragma unroll
        for (int off = 16; off; off >>= 1) {
            s += __shfl_xor_sync(0xffffffffu, s, off);
            q += __shfl_xor_sync(0xffffffffu, q, off);
        }
        const float mu  = s * (1.f / 128.f);
        const float var = q * (1.f / 128.f) - mu * mu;
        const float rs  = rsqrtf(var + 1e-5f);
        float4 g4 = *reinterpret_cast<const float4*>(lng + lane * 4);
        float4 b4 = *reinterpret_cast<const float4*>(lnb + lane * 4);
        float4 e;
        e.x = (v.x - mu) * rs * g4.x + b4.x;
        e.y = (v.y - mu) * rs * g4.y + b4.y;
        e.z = (v.z - mu) * rs * g4.z + b4.z;
        e.w = (v.w - mu) * rs * g4.w + b4.w;
        *reinterpret_cast<float4*>(&g_E[br][(row0 + w) * ENC + lane * 4]) = e;
    }
}

// ---------------------------------------------------------------------------
// Kernel C: logits[b,n,m] = exp(ls) * dot(e1[b,n], e2[b,m]); both orderings.
// grid = (50 n-pairs, 4 b), block = 128 (4 warps x 25 m). Two n's share each
// e2 load; unroll-5 keeps 10 independent shuffle-reduce chains in flight.
// ---------------------------------------------------------------------------
__global__ void logits_kernel(const float* __restrict__ lsc,
                              float* __restrict__ out)
{
    const int n0   = blockIdx.x * 2;
    const int b    = blockIdx.y;
    const int tid  = threadIdx.x;
    const int wp   = tid >> 5;
    const int lane = tid & 31;

    __shared__ float e1s[2][ENC];
    e1s[0][tid] = g_E[0][(b * NPATCH + n0    ) * ENC + tid];
    e1s[1][tid] = g_E[0][(b * NPATCH + n0 + 1) * ENC + tid];
    __syncthreads();

    const float scale = expf(lsc[0]);
    const float4 a0 = reinterpret_cast<const float4*>(e1s[0])[lane];
    const float4 a1 = reinterpret_cast<const float4*>(e1s[1])[lane];

    const int m0 = wp * 25;
    #pragma unroll 5
    for (int m = m0; m < m0 + 25; m++) {
        float4 v = *reinterpret_cast<const float4*>(
            &g_E[1][(b * NPATCH + m) * ENC + lane * 4]);
        float s0 = a0.x * v.x + a0.y * v.y + a0.z * v.z + a0.w * v.w;
        float s1 = a1.x * v.x + a1.y * v.y + a1.z * v.z + a1.w * v.w;
        #pragma unroll
        for (int off = 16; off; off >>= 1) {
            s0 += __shfl_xor_sync(0xffffffffu, s0, off);
            s1 += __shfl_xor_sync(0xffffffffu, s1, off);
        }
        if (lane == 0) {
            float v0 = scale * s0;
            float v1 = scale * s1;
            out[(b * NPATCH + n0    ) * NPATCH + m] = v0;
            out[(b * NPATCH + n0 + 1) * NPATCH + m] = v1;
            float* outT = out + BATCH * NPATCH * NPATCH;
            outT[(b * NPATCH + m) * NPATCH + n0    ] = v0;
            outT[(b * NPATCH + m) * NPATCH + n0 + 1] = v1;
        }
    }
}

// ---------------------------------------------------------------------------
extern "C" void kernel_launch(void* const* d_in, const int* in_sizes, int n_in,
                              void* d_out, int out_size)
{
    const float* f1  = (const float*)d_in[0];   // feat_c1
    const float* f2  = (const float*)d_in[1];   // feat_c2
    // d_in[2] = mask_c1 (all ones; grid static: nv=nh=10)
    const float* icw = (const float*)d_in[3];   // img_conv_w
    const float* icb = (const float*)d_in[4];   // img_conv_b
    const float* iw1 = (const float*)d_in[5];   // img_w1
    const float* iw2 = (const float*)d_in[6];   // img_w2
    const float* ig  = (const float*)d_in[7];   // img_ln_g
    const float* ib  = (const float*)d_in[8];   // img_ln_b
    const float* dcw = (const float*)d_in[9];   // depth_conv_w
    const float* dcb = (const float*)d_in[10];  // depth_conv_b
    const float* dw1 = (const float*)d_in[11];  // depth_w1
    const float* dw2 = (const float*)d_in[12];  // depth_w2
    const float* dg  = (const float*)d_in[13];  // depth_ln_g
    const float* db  = (const float*)d_in[14];  // depth_ln_b
    const float* ls  = (const float*)d_in[15];  // logit_scale

    conv_kernel  <<<dim3(CONVBLK + TPB, 2), 128>>>(f1, f2, icw, icb, dcw, dcb,
                                                   iw1, iw2, dw1, dw2);
    mlp_kernel   <<<dim3(50, 2), 256>>>(ig, ib, dg, db);
    logits_kernel<<<dim3(50, 4), 128>>>(ls, (float*)d_out);
}

// round 5
// speedup vs baseline: 1.3114x; 1.3114x over previous
#include <cuda_runtime.h>
#include <cstdint>

#define CPS    16
#define ENC    128
#define BATCH  4
#define HW     160
#define PLANE  (HW * HW)          // 25600
#define NGRID  10
#define NPATCH 100
#define NROWS  (BATCH * NPATCH)   // 400
#define CCH    256
#define BR     8                  // rows per MLP block
#define TPB     4                 // transpose helper blocks per branch
#define CONVBLK 800               // conv blocks per branch (102400 thr / 128)

// Scratch (allocation-free)
__device__ float g_X[2][NROWS * CCH];          // conv output, patch-major
__device__ float g_E[2][NROWS * ENC];          // embeddings
__device__ float g_W1T[2][CCH * CCH];          // W1 transposed: [k][j]
__device__ float g_W2T[2][CCH * ENC];          // W2 transposed: [k][o]

// ---------------------------------------------------------------------------
// Kernel A: 1x1 conv (channel reduction) + bias + relu, patch-reordered write.
// HBM-bound: reads 210 MB once. SCALAR loads, 1 position/thread ->
// 6400 warps (~43/SM), ~1-1.5 KB in flight per warp => >2x the ~50KB/SM
// needed to saturate HBM. First TPB blocks per branch transpose W
// (hidden under the HBM-bound main work).
// ---------------------------------------------------------------------------
__global__ void __launch_bounds__(128, 10)
conv_kernel(const float* __restrict__ f1,
            const float* __restrict__ f2,
            const float* __restrict__ w_img,
            const float* __restrict__ b_img,
            const float* __restrict__ w_dep,
            const float* __restrict__ b_dep,
            const float* __restrict__ iw1,
            const float* __restrict__ iw2,
            const float* __restrict__ dw1,
            const float* __restrict__ dw2)
{
    const int br  = blockIdx.y;
    const int tid = threadIdx.x;

    if (blockIdx.x < TPB) {
        // ---- weight transpose side-blocks (scheduled first, run under conv)
        const int tb = blockIdx.x;
        const float* __restrict__ W1 = br ? dw1 : iw1;    // [j][k] 256x256
        const float* __restrict__ W2 = br ? dw2 : iw2;    // [o][k] 128x256
        float* __restrict__ W1T = g_W1T[br];
        float* __restrict__ W2T = g_W2T[br];
        for (int idx = tb * 128 + tid; idx < CCH * CCH; idx += TPB * 128) {
            int k = idx >> 8, j = idx & 255;
            W1T[idx] = W1[j * CCH + k];                   // W1T[k][j]
        }
        for (int idx = tb * 128 + tid; idx < CCH * ENC; idx += TPB * 128) {
            int k = idx >> 7, o = idx & 127;
            W2T[idx] = W2[o * CCH + k];                   // W2T[k][o]
        }
        return;
    }

    const float* __restrict__ feat = br ? f2 : f1;
    const float* __restrict__ cw   = br ? w_dep : w_img;
    const float  bias              = br ? b_dep[0] : b_img[0];

    __shared__ float ws[CCH];
    ws[tid]       = cw[tid];
    ws[tid + 128] = cw[tid + 128];
    __syncthreads();

    const int g     = (blockIdx.x - TPB) * 128 + tid;  // 0..102399
    const int plane = g % PLANE;
    const int b     = g / PLANE;

    const float* __restrict__ base =
        feat + (size_t)b * CCH * PLANE + plane;

    float acc0 = 0.f, acc1 = 0.f;
    #pragma unroll 16
    for (int c = 0; c < CCH; c += 2) {
        float v0 = base[(size_t)c * PLANE];
        float v1 = base[(size_t)(c + 1) * PLANE];
        acc0 = fmaf(ws[c],     v0, acc0);
        acc1 = fmaf(ws[c + 1], v1, acc1);
    }
    float a = fmaxf(acc0 + acc1 + bias, 0.f);

    const int y  = plane / HW;
    const int x  = plane % HW;
    const int pv = y >> 4, i = y & 15;
    const int ph = x >> 4, j = x & 15;
    const int p  = (b * NGRID + pv) * NGRID + ph;
    g_X[br][(p << 8) + (i << 4) + j] = a;
}

// ---------------------------------------------------------------------------
// Kernel B: per-branch MLP  relu(X @ W1^T) @ W2^T  + LayerNorm(128).
// grid = (50, 2), block = 256, 8 rows per block. Scalar FFMA.
// Transposed W -> coalesced 128B warp loads (1 line/LDG instead of 32).
// ---------------------------------------------------------------------------
__global__ void __launch_bounds__(256)
mlp_kernel(const float* __restrict__ g_img,
           const float* __restrict__ be_img,
           const float* __restrict__ g_dep,
           const float* __restrict__ be_dep)
{
    const int br  = blockIdx.y;
    const float* __restrict__ W1T = g_W1T[br];
    const float* __restrict__ W2T = g_W2T[br];
    const float* __restrict__ lng = br ? g_dep  : g_img;
    const float* __restrict__ lnb = br ? be_dep : be_img;

    const int row0 = blockIdx.x * BR;
    const int tid  = threadIdx.x;

    __shared__ float xsT[CCH * BR];   // [k][r]
    __shared__ float hsT[CCH * BR];   // [k][r]
    __shared__ float os [BR * ENC];   // [r][o]

    // load X rows transposed (coalesced reads)
    #pragma unroll
    for (int i = 0; i < BR; i++)
        xsT[tid * BR + i] = g_X[br][(row0 + i) * CCH + tid];
    __syncthreads();

    // GEMM1: h[r][j] = relu( sum_k x[r][k] * W1[j][k] ),  j = tid
    {
        float acc[BR];
        #pragma unroll
        for (int r = 0; r < BR; r++) acc[r] = 0.f;

        const float* __restrict__ wp = W1T + tid;     // W1T[k*256 + j]
        #pragma unroll 8
        for (int k = 0; k < CCH; k++) {
            float w = __ldg(wp + k * CCH);            // 1 line per warp-load
            float4 xa = *reinterpret_cast<const float4*>(&xsT[k * BR]);
            float4 xb = *reinterpret_cast<const float4*>(&xsT[k * BR + 4]);
            acc[0] = fmaf(w, xa.x, acc[0]);
            acc[1] = fmaf(w, xa.y, acc[1]);
            acc[2] = fmaf(w, xa.z, acc[2]);
            acc[3] = fmaf(w, xa.w, acc[3]);
            acc[4] = fmaf(w, xb.x, acc[4]);
            acc[5] = fmaf(w, xb.y, acc[5]);
            acc[6] = fmaf(w, xb.z, acc[6]);
            acc[7] = fmaf(w, xb.w, acc[7]);
        }
        float4 h0, h1;
        h0.x = fmaxf(acc[0], 0.f); h0.y = fmaxf(acc[1], 0.f);
        h0.z = fmaxf(acc[2], 0.f); h0.w = fmaxf(acc[3], 0.f);
        h1.x = fmaxf(acc[4], 0.f); h1.y = fmaxf(acc[5], 0.f);
        h1.z = fmaxf(acc[6], 0.f); h1.w = fmaxf(acc[7], 0.f);
        *reinterpret_cast<float4*>(&hsT[tid * BR])     = h0;
        *reinterpret_cast<float4*>(&hsT[tid * BR + 4]) = h1;
    }
    __syncthreads();

    // GEMM2: out[r][o] = sum_k h[r][k] * W2[o][k]
    {
        const int o  = tid & 127;
        const int rb = (tid >> 7) * 4;                // rows rb..rb+3
        float acc[4] = {0.f, 0.f, 0.f, 0.f};
        const float* __restrict__ wp = W2T + o;       // W2T[k*128 + o]
        #pragma unroll 8
        for (int k = 0; k < CCH; k++) {
            float w = __ldg(wp + k * ENC);
            float4 hv = *reinterpret_cast<const float4*>(&hsT[k * BR + rb]);
            acc[0] = fmaf(w, hv.x, acc[0]);
            acc[1] = fmaf(w, hv.y, acc[1]);
            acc[2] = fmaf(w, hv.z, acc[2]);
            acc[3] = fmaf(w, hv.w, acc[3]);
        }
        #pragma unroll
        for (int i = 0; i < 4; i++)
            os[(rb + i) * ENC + o] = acc[i];
    }
    __syncthreads();

    // LayerNorm: warp w handles row w
    {
        const int w    = tid >> 5;
        const int lane = tid & 31;
        float4 v = *reinterpret_cast<const float4*>(&os[w * ENC + lane * 4]);
        float s = v.x + v.y + v.z + v.w;
        float q = v.x * v.x + v.y * v.y + v.z * v.z + v.w * v.w;
        #pragma unroll
        for (int off = 16; off; off >>= 1) {
            s += __shfl_xor_sync(0xffffffffu, s, off);
            q += __shfl_xor_sync(0xffffffffu, q, off);
        }
        const float mu  = s * (1.f / 128.f);
        const float var = q * (1.f / 128.f) - mu * mu;
        const float rs  = rsqrtf(var + 1e-5f);
        float4 g4 = *reinterpret_cast<const float4*>(lng + lane * 4);
        float4 b4 = *reinterpret_cast<const float4*>(lnb + lane * 4);
        float4 e;
        e.x = (v.x - mu) * rs * g4.x + b4.x;
        e.y = (v.y - mu) * rs * g4.y + b4.y;
        e.z = (v.z - mu) * rs * g4.z + b4.z;
        e.w = (v.w - mu) * rs * g4.w + b4.w;
        *reinterpret_cast<float4*>(&g_E[br][(row0 + w) * ENC + lane * 4]) = e;
    }
}

// ---------------------------------------------------------------------------
// Kernel C: logits[b,n,m] = exp(ls) * dot(e1[b,n], e2[b,m]); both orderings.
// grid = (50 n-pairs, 4 b), block = 128 (4 warps x 25 m). Two n's share each
// e2 load; unroll-5 keeps independent shuffle-reduce chains in flight.
// ---------------------------------------------------------------------------
__global__ void logits_kernel(const float* __restrict__ lsc,
                              float* __restrict__ out)
{
    const int n0   = blockIdx.x * 2;
    const int b    = blockIdx.y;
    const int tid  = threadIdx.x;
    const int wp   = tid >> 5;
    const int lane = tid & 31;

    __shared__ float e1s[2][ENC];
    e1s[0][tid] = g_E[0][(b * NPATCH + n0    ) * ENC + tid];
    e1s[1][tid] = g_E[0][(b * NPATCH + n0 + 1) * ENC + tid];
    __syncthreads();

    const float scale = expf(lsc[0]);
    const float4 a0 = reinterpret_cast<const float4*>(e1s[0])[lane];
    const float4 a1 = reinterpret_cast<const float4*>(e1s[1])[lane];

    const int m0 = wp * 25;
    #pragma unroll 5
    for (int m = m0; m < m0 + 25; m++) {
        float4 v = *reinterpret_cast<const float4*>(
            &g_E[1][(b * NPATCH + m) * ENC + lane * 4]);
        float s0 = a0.x * v.x + a0.y * v.y + a0.z * v.z + a0.w * v.w;
        float s1 = a1.x * v.x + a1.y * v.y + a1.z * v.z + a1.w * v.w;
        #pragma unroll
        for (int off = 16; off; off >>= 1) {
            s0 += __shfl_xor_sync(0xffffffffu, s0, off);
            s1 += __shfl_xor_sync(0xffffffffu, s1, off);
        }
        if (lane == 0) {
            float v0 = scale * s0;
            float v1 = scale * s1;
            out[(b * NPATCH + n0    ) * NPATCH + m] = v0;
            out[(b * NPATCH + n0 + 1) * NPATCH + m] = v1;
            float* outT = out + BATCH * NPATCH * NPATCH;
            outT[(b * NPATCH + m) * NPATCH + n0    ] = v0;
            outT[(b * NPATCH + m) * NPATCH + n0 + 1] = v1;
        }
    }
}

// ---------------------------------------------------------------------------
extern "C" void kernel_launch(void* const* d_in, const int* in_sizes, int n_in,
                              void* d_out, int out_size)
{
    const float* f1  = (const float*)d_in[0];   // feat_c1
    const float* f2  = (const float*)d_in[1];   // feat_c2
    // d_in[2] = mask_c1 (all ones; grid static: nv=nh=10)
    const float* icw = (const float*)d_in[3];   // img_conv_w
    const float* icb = (const float*)d_in[4];   // img_conv_b
    const float* iw1 = (const float*)d_in[5];   // img_w1
    const float* iw2 = (const float*)d_in[6];   // img_w2
    const float* ig  = (const float*)d_in[7];   // img_ln_g
    const float* ib  = (const float*)d_in[8];   // img_ln_b
    const float* dcw = (const float*)d_in[9];   // depth_conv_w
    const float* dcb = (const float*)d_in[10];  // depth_conv_b
    const float* dw1 = (const float*)d_in[11];  // depth_w1
    const float* dw2 = (const float*)d_in[12];  // depth_w2
    const float* dg  = (const float*)d_in[13];  // depth_ln_g
    const float* db  = (const float*)d_in[14];  // depth_ln_b
    const float* ls  = (const float*)d_in[15];  // logit_scale

    conv_kernel  <<<dim3(CONVBLK + TPB, 2), 128>>>(f1, f2, icw, icb, dcw, dcb,
                                                   iw1, iw2, dw1, dw2);
    mlp_kernel   <<<dim3(50, 2), 256>>>(ig, ib, dg, db);
    logits_kernel<<<dim3(50, 4), 128>>>(ls, (float*)d_out);
}

// round 7
// speedup vs baseline: 1.5901x; 1.2125x over previous
#include <cuda_runtime.h>
#include <cstdint>

#define CPS    16
#define ENC    128
#define BATCH  4
#define HW     160
#define PLANE  (HW * HW)          // 25600
#define NGRID  10
#define NPATCH 100
#define NROWS  (BATCH * NPATCH)   // 400
#define CCH    256
#define BR     8                  // rows per MLP block

// Scratch (allocation-free): conv output X (2 branches x 400 x 256),
// embeddings E (2 branches x 400 x 128)
__device__ float g_X[2][NROWS * CCH];
__device__ float g_E[2][NROWS * ENC];

// ---------------------------------------------------------------------------
// Kernel A: 1x1 conv (channel reduction) + bias + relu, patch-reordered write.
// HBM-bound: reads 210 MB once.  256 threads x float2 => each block covers a
// full 2KB DRAM grain per channel iteration (row-buffer friendly), grid
// (200,2) = 400 blocks => ~21.6 warps/SM (measured BW plateau).  __ldcs
// (evict-first) keeps the one-shot stream from churning L2.
// ---------------------------------------------------------------------------
__global__ void conv_kernel(const float* __restrict__ f1,
                            const float* __restrict__ f2,
                            const float* __restrict__ w_img,
                            const float* __restrict__ b_img,
                            const float* __restrict__ w_dep,
                            const float* __restrict__ b_dep)
{
    const int br  = blockIdx.y;
    const float* __restrict__ feat = br ? f2 : f1;
    const float* __restrict__ cw   = br ? w_dep : w_img;
    const float  bias              = br ? b_dep[0] : b_img[0];

    __shared__ float ws[CCH];
    const int tid = threadIdx.x;
    ws[tid] = cw[tid];
    __syncthreads();

    const int g     = blockIdx.x * 256 + tid;   // 0..51199 (position pairs)
    const int pos   = g * 2;
    const int plane = pos % PLANE;
    const int b     = pos / PLANE;

    const float* __restrict__ base =
        feat + (size_t)b * CCH * PLANE + plane;

    float a0 = 0.f, a1 = 0.f;
    #pragma unroll 8
    for (int c = 0; c < CCH; c++) {
        float2 v = __ldcs(reinterpret_cast<const float2*>(base + (size_t)c * PLANE));
        float  w = ws[c];
        a0 = fmaf(w, v.x, a0);
        a1 = fmaf(w, v.y, a1);
    }
    a0 = fmaxf(a0 + bias, 0.f);
    a1 = fmaxf(a1 + bias, 0.f);

    const int y  = plane / HW;
    const int x  = plane % HW;                 // even
    const int pv = y >> 4, i = y & 15;
    const int ph = x >> 4, j = x & 15;         // j even, j+1 same patch
    const int p  = (b * NGRID + pv) * NGRID + ph;
    float2 o; o.x = a0; o.y = a1;
    *reinterpret_cast<float2*>(&g_X[br][(p << 8) + (i << 4) + j]) = o;
}

// ---------------------------------------------------------------------------
// Kernel B (R3-proven): per-branch MLP relu(X @ W1^T) @ W2^T + LayerNorm(128).
// grid = (50, 2), block = 256, 8 rows per block.
// ---------------------------------------------------------------------------
__global__ void mlp_kernel(const float* __restrict__ w1_img,
                           const float* __restrict__ w2_img,
                           const float* __restrict__ g_img,
                           const float* __restrict__ be_img,
                           const float* __restrict__ w1_dep,
                           const float* __restrict__ w2_dep,
                           const float* __restrict__ g_dep,
                           const float* __restrict__ be_dep)
{
    const int br = blockIdx.y;
    const float* __restrict__ W1  = br ? w1_dep : w1_img;
    const float* __restrict__ W2  = br ? w2_dep : w2_img;
    const float* __restrict__ lng = br ? g_dep  : g_img;
    const float* __restrict__ lnb = br ? be_dep : be_img;

    const int row0 = blockIdx.x * BR;
    const int tid  = threadIdx.x;

    __shared__ float xsT[CCH * BR];   // [k][r]
    __shared__ float hsT[CCH * BR];   // [k][r]
    __shared__ float os [BR * ENC];   // [r][o]

    // load X rows transposed
    for (int t = tid; t < CCH * BR; t += 256) {
        int r = t >> 8, k = t & 255;
        xsT[k * BR + r] = g_X[br][(row0 + r) * CCH + k];
    }
    __syncthreads();

    // GEMM1: h[r][j] = relu( sum_k x[r][k] * W1[j][k] ),  j = tid
    {
        const int j = tid;
        const float4* __restrict__ w1r =
            reinterpret_cast<const float4*>(W1 + j * CCH);
        float acc[BR];
        #pragma unroll
        for (int r = 0; r < BR; r++) acc[r] = 0.f;

        #pragma unroll 4
        for (int k4 = 0; k4 < CCH / 4; k4++) {
            float4 w = w1r[k4];
            float wv[4]; wv[0] = w.x; wv[1] = w.y; wv[2] = w.z; wv[3] = w.w;
            const float* xk = &xsT[k4 * 4 * BR];
            #pragma unroll
            for (int kk = 0; kk < 4; kk++) {
                float  c  = wv[kk];
                float4 xa = *reinterpret_cast<const float4*>(xk + kk * BR);
                float4 xb = *reinterpret_cast<const float4*>(xk + kk * BR + 4);
                acc[0] = fmaf(c, xa.x, acc[0]);
                acc[1] = fmaf(c, xa.y, acc[1]);
                acc[2] = fmaf(c, xa.z, acc[2]);
                acc[3] = fmaf(c, xa.w, acc[3]);
                acc[4] = fmaf(c, xb.x, acc[4]);
                acc[5] = fmaf(c, xb.y, acc[5]);
                acc[6] = fmaf(c, xb.z, acc[6]);
                acc[7] = fmaf(c, xb.w, acc[7]);
            }
        }
        float4 h0, h1;
        h0.x = fmaxf(acc[0], 0.f); h0.y = fmaxf(acc[1], 0.f);
        h0.z = fmaxf(acc[2], 0.f); h0.w = fmaxf(acc[3], 0.f);
        h1.x = fmaxf(acc[4], 0.f); h1.y = fmaxf(acc[5], 0.f);
        h1.z = fmaxf(acc[6], 0.f); h1.w = fmaxf(acc[7], 0.f);
        *reinterpret_cast<float4*>(&hsT[j * BR])     = h0;
        *reinterpret_cast<float4*>(&hsT[j * BR + 4]) = h1;
    }
    __syncthreads();

    // GEMM2: out[r][o] = sum_k h[r][k] * W2[o][k]
    {
        const int o    = tid & 127;
        const int rb   = (tid >> 7) * 4;        // 0 or 4
        const float4* __restrict__ w2r =
            reinterpret_cast<const float4*>(W2 + o * CCH);
        float acc[4] = {0.f, 0.f, 0.f, 0.f};

        #pragma unroll 4
        for (int k4 = 0; k4 < CCH / 4; k4++) {
            float4 w = w2r[k4];
            float wv[4]; wv[0] = w.x; wv[1] = w.y; wv[2] = w.z; wv[3] = w.w;
            const float* hk = &hsT[k4 * 4 * BR + rb];
            #pragma unroll
            for (int kk = 0; kk < 4; kk++) {
                float  c  = wv[kk];
                float4 hv = *reinterpret_cast<const float4*>(hk + kk * BR);
                acc[0] = fmaf(c, hv.x, acc[0]);
                acc[1] = fmaf(c, hv.y, acc[1]);
                acc[2] = fmaf(c, hv.z, acc[2]);
                acc[3] = fmaf(c, hv.w, acc[3]);
            }
        }
        #pragma unroll
        for (int i = 0; i < 4; i++)
            os[(rb + i) * ENC + o] = acc[i];
    }
    __syncthreads();

    // LayerNorm: warp w handles row w
    {
        const int w    = tid >> 5;
        const int lane = tid & 31;
        float4 v = *reinterpret_cast<const float4*>(&os[w * ENC + lane * 4]);
        float s = v.x + v.y + v.z + v.w;
        float q = v.x * v.x + v.y * v.y + v.z * v.z + v.w * v.w;
        #pragma unroll
        for (int off = 16; off; off >>= 1) {
            s += __shfl_xor_sync(0xffffffffu, s, off);
            q += __shfl_xor_sync(0xffffffffu, q, off);
        }
        const float mu  = s * (1.f / 128.f);
        const float var = q * (1.f / 128.f) - mu * mu;
        const float rs  = rsqrtf(var + 1e-5f);
        float4 g4 = *reinterpret_cast<const float4*>(lng + lane * 4);
        float4 b4 = *reinterpret_cast<const float4*>(lnb + lane * 4);
        float4 e;
        e.x = (v.x - mu) * rs * g4.x + b4.x;
        e.y = (v.y - mu) * rs * g4.y + b4.y;
        e.z = (v.z - mu) * rs * g4.z + b4.z;
        e.w = (v.w - mu) * rs * g4.w + b4.w;
        *reinterpret_cast<float4*>(&g_E[br][(row0 + w) * ENC + lane * 4]) = e;
    }
}

// ---------------------------------------------------------------------------
// Kernel C (R3-proven): logits[b,n,m] = exp(ls) * dot(e1[b,n], e2[b,m]);
// writes both orderings. grid = (100 n, 4 b), block = 128 (4 warps x 25 m).
// ---------------------------------------------------------------------------
__global__ void logits_kernel(const float* __restrict__ lsc,
                              float* __restrict__ out)
{
    const int n    = blockIdx.x;
    const int b    = blockIdx.y;
    const int tid  = threadIdx.x;
    const int wp   = tid >> 5;
    const int lane = tid & 31;

    __shared__ float e1s[ENC];
    e1s[tid] = g_E[0][(b * NPATCH + n) * ENC + tid];
    __syncthreads();

    const float scale = expf(lsc[0]);
    const float4 a = reinterpret_cast<const float4*>(e1s)[lane];

    const int m0 = wp * 25;
    for (int m = m0; m < m0 + 25; m++) {
        float4 v = *reinterpret_cast<const float4*>(
            &g_E[1][(b * NPATCH + m) * ENC + lane * 4]);
        float s = a.x * v.x + a.y * v.y + a.z * v.z + a.w * v.w;
        #pragma unroll
        for (int off = 16; off; off >>= 1)
            s += __shfl_xor_sync(0xffffffffu, s, off);
        if (lane == 0) {
            float val = scale * s;
            out[(b * NPATCH + n) * NPATCH + m] = val;                       // bnm
            out[BATCH * NPATCH * NPATCH + (b * NPATCH + m) * NPATCH + n] = val;  // bmn
        }
    }
}

// ---------------------------------------------------------------------------
extern "C" void kernel_launch(void* const* d_in, const int* in_sizes, int n_in,
                              void* d_out, int out_size)
{
    const float* f1  = (const float*)d_in[0];   // feat_c1
    const float* f2  = (const float*)d_in[1];   // feat_c2
    // d_in[2] = mask_c1 (all ones; grid static: nv=nh=10)
    const float* icw = (const float*)d_in[3];   // img_conv_w
    const float* icb = (const float*)d_in[4];   // img_conv_b
    const float* iw1 = (const float*)d_in[5];   // img_w1
    const float* iw2 = (const float*)d_in[6];   // img_w2
    const float* ig  = (const float*)d_in[7];   // img_ln_g
    const float* ib  = (const float*)d_in[8];   // img_ln_b
    const float* dcw = (const float*)d_in[9];   // depth_conv_w
    const float* dcb = (const float*)d_in[10];  // depth_conv_b
    const float* dw1 = (const float*)d_in[11];  // depth_w1
    const float* dw2 = (const float*)d_in[12];  // depth_w2
    const float* dg  = (const float*)d_in[13];  // depth_ln_g
    const float* db  = (const float*)d_in[14];  // depth_ln_b
    const float* ls  = (const float*)d_in[15];  // logit_scale

    conv_kernel  <<<dim3(200, 2), 256>>>(f1, f2, icw, icb, dcw, dcb);
    mlp_kernel   <<<dim3(50, 2), 256>>>(iw1, iw2, ig, ib, dw1, dw2, dg, db);
    logits_kernel<<<dim3(100, 4), 128>>>(ls, (float*)d_out);
}